// round 15
// baseline (speedup 1.0000x reference)
#include <cuda_runtime.h>
#include <cuda_bf16.h>

// WaveletParsingLayer: x3 [B=128, N_SEG=128, SEG_LEN=2048] f32, tail half
// (k >= 1024) of each segment is the filler 10.1f. Output [B, N_SEG*1024]
// == strided copy of the first 1024 f32 of each 2048-f32 segment.
//
// R14: copy-engine experiment. The SM kernel is at ~89% of DRAM spec
// (134 MB / 18.9 us = 7.1 TB/s) and every SM-side lever (MLP batching,
// 5 cache-policy variants, single-wave launch) moved <=5%. The access
// pattern is exactly a pitched 2D copy:
//   16384 rows x 4096 B, src pitch 8192 B, dst pitch 4096 B
// cudaMemcpy2DAsync D2D is graph-capturable and allowed by the harness
// contract ("cudaMemcpyAsync device-to-device ... are fine"). It runs on
// the copy engines: zero SM involvement, no L2 replacement fight.
// If CE sustains near-peak DRAM for 4 KB rows -> ~17 us; if CE-limited,
// revert to the R12 kernel (18.94 us) next round.

extern "C" void kernel_launch(void* const* d_in, const int* in_sizes, int n_in,
                              void* d_out, int out_size)
{
    // metadata order: x1 [128,64] f32 (unused), x2 [128,64] f32 (unused),
    //                 x3 [128,128,2048] f32
    const char* x3 = (const char*)d_in[2];
    char* out = (char*)d_out;

    // 128*128 = 16384 segments; copy first 4096 B of each 8192 B segment.
    cudaMemcpy2DAsync(out, 4096,            // dst, dst pitch
                      x3, 8192,             // src, src pitch
                      4096, 16384,          // width (bytes), height (rows)
                      cudaMemcpyDeviceToDevice,
                      0);
}

// round 17
// speedup vs baseline: 3.7646x; 3.7646x over previous
#include <cuda_runtime.h>
#include <cuda_bf16.h>

// WaveletParsingLayer: x3 [B=128, N_SEG=128, SEG_LEN=2048] f32, tail half
// (k >= 1024) of each segment is the filler 10.1f. Output [B, N_SEG*1024]
// == strided copy of the first 1024 f32 of each 2048-f32 segment.
//
// float4 units: o4 = (b*128+s)*256 + k4 ; src4 = ((o4>>8)<<9) | (o4&255)
// total out f4 = 4,194,304 = 1024 blocks * 256 threads * 16
//
// R15: revert to measured-best R12 configuration (18.94 us). Full sweep
// results: plain 22.5 | ldcs 21.2 | ldg/stcs 2-wave 19.2 | THIS 18.94 |
// evict_last-256b 25.3 | stwt 23.3 | copy-engine memcpy2D 72.2.
// At 18.9 us this kernel sustains 7.1 TB/s (89% of DRAM spec) moving the
// mandatory 134 MB — the practical cold-DRAM roofline. Replay L2 reuse is
// structurally impossible (134 MB live set > 126 MB L2; timed == cold
// profiled dur at this config). Converged.
//
// Config: single wave (1024 CTAs < 1184 concurrent @ 8 CTAs/SM),
// 16 f4/thread as two 8-deep front-batched load passes (MLP=8),
// __ldg reads + __stcs streaming stores, regs pinned to 32 via
// __launch_bounds__(256, 8).

__global__ __launch_bounds__(256, 8) void wavelet_compact_copy(
    const float4* __restrict__ src, float4* __restrict__ dst)
{
    unsigned cta_base = blockIdx.x * 4096u + threadIdx.x;

#pragma unroll
    for (int half = 0; half < 2; ++half) {
        unsigned base = cta_base + (unsigned)half * 2048u;
        float4 v[8];
#pragma unroll
        for (int i = 0; i < 8; ++i) {
            unsigned o4 = base + (unsigned)i * 256u;
            unsigned s4 = ((o4 >> 8) << 9) | (o4 & 255u);
            v[i] = __ldg(&src[s4]);
        }
#pragma unroll
        for (int i = 0; i < 8; ++i) {
            unsigned o4 = base + (unsigned)i * 256u;
            __stcs(&dst[o4], v[i]);
        }
    }
}

extern "C" void kernel_launch(void* const* d_in, const int* in_sizes, int n_in,
                              void* d_out, int out_size)
{
    // metadata order: x1 [128,64] f32 (unused), x2 [128,64] f32 (unused),
    //                 x3 [128,128,2048] f32
    const float4* x3 = (const float4*)d_in[2];
    float4* out = (float4*)d_out;

    wavelet_compact_copy<<<1024, 256>>>(x3, out);
}